// round 2
// baseline (speedup 1.0000x reference)
#include <cuda_runtime.h>
#include <math.h>

#define N_ENT 100000
#define KN 64
#define DD 500
#define TWO_D 1000
#define RR 237
#define AT 128
#define BB 1024

// ---- device scratch (no allocations allowed) ----
__device__ int   g_bool_mode;          // 0=int32, 1=byte, 2=float32
__device__ float g_cos[RR * DD];
__device__ float g_sin[RR * DD];
__device__ float g_u[BB * TWO_D];      // u_i = Wk^T (Wq e_i)  [B, 2D]

__device__ __forceinline__ int get_flag(const void* p, size_t i, int mode) {
    if (mode == 1) return ((const unsigned char*)p)[i] != 0;
    if (mode == 2) return ((const float*)p)[i] != 0.0f;
    return ((const int*)p)[i] != 0;
}

// Disambiguate bool storage: int32 words are always <=1; byte-packed bool words
// exceed 1 (but never 0x01010101) w.h.p. over 2048 words; float 1.0f = 0x3F800000.
__global__ void detect_bool_kernel(const unsigned int* __restrict__ p) {
    __shared__ int big1, big2;
    if (threadIdx.x == 0) { big1 = 0; big2 = 0; }
    __syncthreads();
    for (int i = threadIdx.x; i < 2048; i += blockDim.x) {
        unsigned v = p[i];
        if (v > 1u)          big1 = 1;
        if (v > 0x01010101u) big2 = 1;
    }
    __syncthreads();
    if (threadIdx.x == 0) g_bool_mode = big2 ? 2 : (big1 ? 1 : 0);
}

__global__ void trig_kernel(const float* __restrict__ phase) {
    int i = blockIdx.x * blockDim.x + threadIdx.x;
    if (i < RR * DD) {
        float ph = phase[i];
        g_cos[i] = cosf(ph);
        g_sin[i] = sinf(ph);
    }
}

// Fused: q = Wq e_i (per anchor), then u = Wk^T q. 8 anchors per block so the
// 512KB Wq/Wk matrices are read from L2 only 128 times (64MB) instead of 1024.
__global__ __launch_bounds__(256) void qu_kernel(
    const int*   __restrict__ anchor_ids,
    const float* __restrict__ E,
    const float* __restrict__ Wq,
    const float* __restrict__ Wk)
{
    __shared__ float e_sm[8][TWO_D];
    __shared__ float q_sm[8][AT];
    __shared__ int   aid_sm[8];
    int tid  = threadIdx.x;
    int base = blockIdx.x * 8;
    if (tid < 8) aid_sm[tid] = anchor_ids[base + tid];
    __syncthreads();
    for (int idx = tid; idx < 8 * TWO_D; idx += 256) {
        int i = idx / TWO_D;
        int d = idx - i * TWO_D;
        e_sm[i][d] = E[(size_t)aid_sm[i] * TWO_D + d];
    }
    __syncthreads();

    int warp = tid >> 5, lane = tid & 31;
    // Phase 1: q[i][a]. 4 passes, each warp owns 4 consecutive a-rows, e in regs.
    for (int p = 0; p < 4; p++) {
        int a0 = p * 32 + warp * 4;
        float acc[4][8];
        #pragma unroll
        for (int r = 0; r < 4; r++)
            #pragma unroll
            for (int i = 0; i < 8; i++) acc[r][i] = 0.f;
        for (int d = lane; d < TWO_D; d += 32) {
            float ev[8];
            #pragma unroll
            for (int i = 0; i < 8; i++) ev[i] = e_sm[i][d];
            #pragma unroll
            for (int r = 0; r < 4; r++) {
                float wv = Wq[(a0 + r) * TWO_D + d];
                #pragma unroll
                for (int i = 0; i < 8; i++) acc[r][i] += wv * ev[i];
            }
        }
        #pragma unroll
        for (int r = 0; r < 4; r++)
            #pragma unroll
            for (int i = 0; i < 8; i++) {
                float v = acc[r][i];
                #pragma unroll
                for (int off = 16; off; off >>= 1)
                    v += __shfl_xor_sync(0xffffffffu, v, off);
                if (lane == 0) q_sm[i][a0 + r] = v;
            }
    }
    __syncthreads();

    // Phase 2: u[i][c] = sum_a Wk[a][c] * q[i][a]. Coalesced Wk columns,
    // broadcast float4 q reads.
    for (int c = tid; c < TWO_D; c += 256) {
        float acc[8] = {0.f,0.f,0.f,0.f,0.f,0.f,0.f,0.f};
        for (int a = 0; a < AT; a += 4) {
            float w0 = Wk[(a+0) * TWO_D + c];
            float w1 = Wk[(a+1) * TWO_D + c];
            float w2 = Wk[(a+2) * TWO_D + c];
            float w3 = Wk[(a+3) * TWO_D + c];
            #pragma unroll
            for (int i = 0; i < 8; i++) {
                float4 q4 = *(const float4*)&q_sm[i][a];
                acc[i] += w0*q4.x + w1*q4.y + w2*q4.z + w3*q4.w;
            }
        }
        #pragma unroll
        for (int i = 0; i < 8; i++)
            g_u[(size_t)(base + i) * TWO_D + c] = acc[i];
    }
}

// Main: block per anchor, online softmax over active neighbors, hat kept in
// registers between the logit dot and the delta accumulation (single gather).
__global__ __launch_bounds__(256) void refine_kernel(
    const int*   __restrict__ anchor_ids,
    const int*   __restrict__ nbr_ent,
    const int*   __restrict__ nbr_rel,
    const void*  __restrict__ nbr_dir,
    const void*  __restrict__ nbr_mask,
    const float* __restrict__ freq,
    const float* __restrict__ E,
    const float* __restrict__ a_param,
    const float* __restrict__ eta_raw,
    const float* __restrict__ w_raw,
    const float* __restrict__ b_p,
    const float* __restrict__ rel_bias,
    const float* __restrict__ dir_bias,
    float*       __restrict__ out)
{
    __shared__ int s_ent[KN];
    __shared__ int s_rel[KN];
    __shared__ unsigned char s_dir[KN];
    __shared__ unsigned char s_msk[KN];
    __shared__ float s_red[8];
    __shared__ float s_ab[2];
    __shared__ float s_S;

    int tid = threadIdx.x;
    int bid = blockIdx.x;
    int aid = anchor_ids[bid];
    int mode = g_bool_mode;
    if (tid < KN) {
        size_t o = (size_t)aid * KN + tid;
        s_ent[tid] = nbr_ent[o];
        s_rel[tid] = nbr_rel[o];
        s_dir[tid] = (unsigned char)get_flag(nbr_dir, o, mode);
        s_msk[tid] = (unsigned char)get_flag(nbr_mask, o, mode);
    }
    __syncthreads();

    int  c   = tid * 2;            // this thread's complex components c, c+1
    bool act = (c < DD);           // threads 0..249 active for vector work
    float2 uRe = make_float2(0.f, 0.f), uIm = make_float2(0.f, 0.f);
    if (act) {
        uRe = *(const float2*)&g_u[(size_t)bid * TWO_D + c];
        uIm = *(const float2*)&g_u[(size_t)bid * TWO_D + DD + c];
    }

    float m = -3.0e38f, S = 0.f;                  // thread 0's softmax state
    float dRe0 = 0.f, dRe1 = 0.f, dIm0 = 0.f, dIm1 = 0.f;

    for (int j = 0; j < KN; j++) {
        if (!s_msk[j]) continue;   // uniform branch; exp(-10000-max)==0 in fp32
        int ent = s_ent[j];
        int rel = s_rel[j];
        int dj  = s_dir[j];
        float rm0 = 0.f, rm1 = 0.f, im0 = 0.f, im1 = 0.f, part = 0.f;
        if (act) {
            const float* erow = E + (size_t)ent * TWO_D;
            float2 re = *(const float2*)(erow + c);
            float2 im = *(const float2*)(erow + DD + c);
            float2 cc = *(const float2*)(g_cos + rel * DD + c);
            float2 ss = *(const float2*)(g_sin + rel * DD + c);
            float sg = dj ? -1.f : 1.f;
            float s0 = ss.x * sg, s1 = ss.y * sg;
            rm0 = re.x * cc.x - im.x * s0;
            rm1 = re.y * cc.y - im.y * s1;
            im0 = re.x * s0 + im.x * cc.x;
            im1 = re.y * s1 + im.y * cc.y;
            part = uRe.x*rm0 + uRe.y*rm1 + uIm.x*im0 + uIm.y*im1;
        }
        #pragma unroll
        for (int off = 16; off; off >>= 1)
            part += __shfl_xor_sync(0xffffffffu, part, off);
        if ((tid & 31) == 0) s_red[tid >> 5] = part;
        __syncthreads();
        if (tid == 0) {
            float dot = s_red[0]+s_red[1]+s_red[2]+s_red[3]
                      + s_red[4]+s_red[5]+s_red[6]+s_red[7];
            float l = dot * 0.08838834764831845f   // 1/sqrt(128)
                    + rel_bias[rel] + dir_bias[dj];
            float mn    = fmaxf(m, l);
            float alpha = __expf(m - mn);
            float pw    = __expf(l - mn);
            S = S * alpha + pw;
            m = mn;
            s_ab[0] = alpha;
            s_ab[1] = pw;
        }
        __syncthreads();
        float alpha = s_ab[0], pw = s_ab[1];
        dRe0 = dRe0 * alpha + pw * rm0;
        dRe1 = dRe1 * alpha + pw * rm1;
        dIm0 = dIm0 * alpha + pw * im0;
        dIm1 = dIm1 * alpha + pw * im1;
    }
    if (tid == 0) s_S = S;
    __syncthreads();
    float Sv = s_S;

    if (act) {
        const float* eirow = E + (size_t)aid * TWO_D;
        float2 eRe = *(const float2*)(eirow + c);
        float2 eIm = *(const float2*)(eirow + DD + c);
        float oRe0, oRe1, oIm0, oIm1;
        if (Sv > 0.f) {
            float wsp = log1pf(expf(w_raw[0]));          // softplus(w_raw)
            float lf  = log1pf(freq[aid]);
            float z   = eta_raw[0] - wsp * lf + b_p[0];
            float eta = 0.5f / (1.f + expf(-z));         // ETA_MAX * sigmoid
            float2 ap = *(const float2*)(a_param + c);
            float inv = 1.f / Sv;
            float dr0 = ap.x * (dRe0 * inv);
            float dr1 = ap.y * (dRe1 * inv);
            float di0 = ap.x * (dIm0 * inv);
            float di1 = ap.y * (dIm1 * inv);
            oRe0 = eRe.x + eta * (dr0 - eRe.x);
            oRe1 = eRe.y + eta * (dr1 - eRe.y);
            oIm0 = eIm.x + eta * (di0 - eIm.x);
            oIm1 = eIm.y + eta * (di1 - eIm.y);
        } else {
            // no neighbors: delta = e_i and eta = 0 -> out = e_i exactly
            oRe0 = eRe.x; oRe1 = eRe.y; oIm0 = eIm.x; oIm1 = eIm.y;
        }
        *(float2*)(out + (size_t)bid * TWO_D + c)      = make_float2(oRe0, oRe1);
        *(float2*)(out + (size_t)bid * TWO_D + DD + c) = make_float2(oIm0, oIm1);
    }
}

extern "C" void kernel_launch(void* const* d_in, const int* in_sizes, int n_in,
                              void* d_out, int out_size) {
    const int*   anchor_ids = (const int*)  d_in[0];
    const int*   nbr_ent    = (const int*)  d_in[1];
    const int*   nbr_rel    = (const int*)  d_in[2];
    const void*  nbr_dir    =               d_in[3];
    const void*  nbr_mask   =               d_in[4];
    const float* freq       = (const float*)d_in[5];
    const float* E          = (const float*)d_in[6];
    const float* rel_phase  = (const float*)d_in[7];
    const float* a_param    = (const float*)d_in[8];
    const float* eta_raw    = (const float*)d_in[9];
    const float* w_raw      = (const float*)d_in[10];
    const float* b_p        = (const float*)d_in[11];
    const float* Wq         = (const float*)d_in[12];
    const float* Wk         = (const float*)d_in[13];
    const float* rel_bias   = (const float*)d_in[14];
    const float* dir_bias   = (const float*)d_in[15];
    float* out = (float*)d_out;

    detect_bool_kernel<<<1, 256>>>((const unsigned int*)d_in[3]);
    trig_kernel<<<(RR * DD + 255) / 256, 256>>>(rel_phase);
    qu_kernel<<<BB / 8, 256>>>(anchor_ids, E, Wq, Wk);
    refine_kernel<<<BB, 256>>>(anchor_ids, nbr_ent, nbr_rel, nbr_dir, nbr_mask,
                               freq, E, a_param, eta_raw, w_raw, b_p,
                               rel_bias, dir_bias, out);
}

// round 3
// speedup vs baseline: 1.0472x; 1.0472x over previous
#include <cuda_runtime.h>
#include <math.h>

#define N_ENT 100000
#define KN 64
#define DD 500
#define F2 250            // float2 count per complex half
#define TWO_D 1000
#define RR 237
#define AT 128
#define BB 1024

#define QU_BLOCKS 128
#define TRIG_BLOCKS ((RR * DD + 255) / 256)    // 463
#define PREP_GRID (QU_BLOCKS + 1 + TRIG_BLOCKS)

// ---- device scratch (no allocations allowed) ----
__device__ int   g_bool_mode;          // 0=int32, 1=byte, 2=float32
__device__ float g_cos[RR * DD];
__device__ float g_sin[RR * DD];
__device__ float g_u[BB * TWO_D];      // u_i = Wk^T (Wq e_i)  [B, 2D]

__device__ __forceinline__ int get_flag(const void* p, size_t i, int mode) {
    if (mode == 1) return ((const unsigned char*)p)[i] != 0;
    if (mode == 2) return ((const float*)p)[i] != 0.0f;
    return ((const int*)p)[i] != 0;
}

// Fused prep: blocks [0,128) = qu, block 128 = bool-mode detect,
// blocks [129, 129+463) = cos/sin tables. One launch instead of three.
__global__ __launch_bounds__(256) void prep_kernel(
    const int*   __restrict__ anchor_ids,
    const float* __restrict__ E,
    const float* __restrict__ Wq,
    const float* __restrict__ Wk,
    const float* __restrict__ phase,
    const unsigned int* __restrict__ boolprobe)
{
    __shared__ float e_sm[8][TWO_D];
    __shared__ float q_sm[8][AT];
    __shared__ int   aid_sm[8];
    int blk = blockIdx.x;
    int tid = threadIdx.x;

    if (blk >= QU_BLOCKS) {
        if (blk == QU_BLOCKS) {
            // bool storage detect: int32 words always <=1; byte-packed bool
            // words exceed 1 w.h.p. but never 0x01010101; float 1.0f=0x3F800000
            __shared__ int big1, big2;
            if (tid == 0) { big1 = 0; big2 = 0; }
            __syncthreads();
            for (int i = tid; i < 2048; i += 256) {
                unsigned v = boolprobe[i];
                if (v > 1u)          big1 = 1;
                if (v > 0x01010101u) big2 = 1;
            }
            __syncthreads();
            if (tid == 0) g_bool_mode = big2 ? 2 : (big1 ? 1 : 0);
        } else {
            int i = (blk - QU_BLOCKS - 1) * 256 + tid;
            if (i < RR * DD) {
                float s, c;
                sincosf(phase[i], &s, &c);
                g_cos[i] = c;
                g_sin[i] = s;
            }
        }
        return;
    }

    // ---- qu: u = Wk^T (Wq e_i), 8 anchors per block ----
    int base = blk * 8;
    if (tid < 8) aid_sm[tid] = anchor_ids[base + tid];
    __syncthreads();
    for (int idx = tid; idx < 8 * TWO_D; idx += 256) {
        int i = idx / TWO_D;
        int d = idx - i * TWO_D;
        e_sm[i][d] = E[(size_t)aid_sm[i] * TWO_D + d];
    }
    __syncthreads();

    int warp = tid >> 5, lane = tid & 31;
    for (int p = 0; p < 4; p++) {
        int a0 = p * 32 + warp * 4;
        float acc[4][8];
        #pragma unroll
        for (int r = 0; r < 4; r++)
            #pragma unroll
            for (int i = 0; i < 8; i++) acc[r][i] = 0.f;
        for (int d = lane; d < TWO_D; d += 32) {
            float ev[8];
            #pragma unroll
            for (int i = 0; i < 8; i++) ev[i] = e_sm[i][d];
            #pragma unroll
            for (int r = 0; r < 4; r++) {
                float wv = Wq[(a0 + r) * TWO_D + d];
                #pragma unroll
                for (int i = 0; i < 8; i++) acc[r][i] += wv * ev[i];
            }
        }
        #pragma unroll
        for (int r = 0; r < 4; r++)
            #pragma unroll
            for (int i = 0; i < 8; i++) {
                float v = acc[r][i];
                #pragma unroll
                for (int off = 16; off; off >>= 1)
                    v += __shfl_xor_sync(0xffffffffu, v, off);
                if (lane == 0) q_sm[i][a0 + r] = v;
            }
    }
    __syncthreads();

    for (int c = tid; c < TWO_D; c += 256) {
        float acc[8] = {0.f,0.f,0.f,0.f,0.f,0.f,0.f,0.f};
        for (int a = 0; a < AT; a += 4) {
            float w0 = Wk[(a+0) * TWO_D + c];
            float w1 = Wk[(a+1) * TWO_D + c];
            float w2 = Wk[(a+2) * TWO_D + c];
            float w3 = Wk[(a+3) * TWO_D + c];
            #pragma unroll
            for (int i = 0; i < 8; i++) {
                float4 q4 = *(const float4*)&q_sm[i][a];
                acc[i] += w0*q4.x + w1*q4.y + w2*q4.z + w3*q4.w;
            }
        }
        #pragma unroll
        for (int i = 0; i < 8; i++)
            g_u[(size_t)(base + i) * TWO_D + c] = acc[i];
    }
}

// Main: block per anchor. Warp w owns neighbors [8w, 8w+8), computes full-row
// logit dot via butterfly reduce, and keeps a warp-local online softmax with a
// register-resident weighted-hat accumulator -> each gathered row is read from
// DRAM exactly once, and there are no per-neighbor block barriers.
__global__ __launch_bounds__(256, 2) void refine_kernel(
    const int*   __restrict__ anchor_ids,
    const int*   __restrict__ nbr_ent,
    const int*   __restrict__ nbr_rel,
    const void*  __restrict__ nbr_dir,
    const void*  __restrict__ nbr_mask,
    const float* __restrict__ freq,
    const float* __restrict__ E,
    const float* __restrict__ a_param,
    const float* __restrict__ eta_raw,
    const float* __restrict__ w_raw,
    const float* __restrict__ b_p,
    const float* __restrict__ rel_bias,
    const float* __restrict__ dir_bias,
    float*       __restrict__ out)
{
    __shared__ int s_ent[KN];
    __shared__ int s_rel[KN];
    __shared__ unsigned char s_dir[KN];
    __shared__ unsigned char s_msk[KN];
    __shared__ float s_u[TWO_D];
    __shared__ float s_m[8];
    __shared__ float s_Sw[8];
    __shared__ float s_acc[8][TWO_D];

    int tid  = threadIdx.x;
    int bid  = blockIdx.x;
    int warp = tid >> 5, lane = tid & 31;
    int aid  = anchor_ids[bid];
    int mode = g_bool_mode;

    if (tid < KN) {
        size_t o = (size_t)aid * KN + tid;
        s_ent[tid] = nbr_ent[o];
        s_rel[tid] = nbr_rel[o];
        s_dir[tid] = (unsigned char)get_flag(nbr_dir, o, mode);
        s_msk[tid] = (unsigned char)get_flag(nbr_mask, o, mode);
    }
    for (int i = tid; i < TWO_D; i += 256)
        s_u[i] = g_u[(size_t)bid * TWO_D + i];
    __syncthreads();

    // lane owns float2 slots f = lane + 32*i, i in [0,8), valid while f < 250
    float2 aRe[8], aIm[8];
    #pragma unroll
    for (int i = 0; i < 8; i++) {
        aRe[i] = make_float2(0.f, 0.f);
        aIm[i] = make_float2(0.f, 0.f);
    }
    float m = -3.0e38f, S = 0.f;

    const float2* u2 = (const float2*)s_u;   // re at [f], im at [F2+f]

    for (int jj = 0; jj < 8; jj++) {
        int j = warp * 8 + jj;
        if (!s_msk[j]) continue;             // uniform within warp
        int ent = s_ent[j];
        int rel = s_rel[j];
        int dj  = s_dir[j];
        const float2* er = (const float2*)(E + (size_t)ent * TWO_D);
        const float2* cr = (const float2*)(g_cos + rel * DD);
        const float2* sr = (const float2*)(g_sin + rel * DD);
        float sg = dj ? -1.f : 1.f;

        float2 hr[8], hi[8];
        float dot = 0.f;
        #pragma unroll
        for (int i = 0; i < 8; i++) {
            int f = lane + 32 * i;
            if (f < F2) {
                float2 re = er[f];
                float2 im = er[F2 + f];
                float2 c  = cr[f];
                float2 s  = sr[f];
                float s0 = s.x * sg, s1 = s.y * sg;
                hr[i].x = re.x * c.x - im.x * s0;
                hr[i].y = re.y * c.y - im.y * s1;
                hi[i].x = re.x * s0 + im.x * c.x;
                hi[i].y = re.y * s1 + im.y * c.y;
                float2 ur = u2[f], ui = u2[F2 + f];
                dot += ur.x*hr[i].x + ur.y*hr[i].y + ui.x*hi[i].x + ui.y*hi[i].y;
            } else {
                hr[i] = make_float2(0.f, 0.f);
                hi[i] = make_float2(0.f, 0.f);
            }
        }
        #pragma unroll
        for (int off = 16; off; off >>= 1)
            dot += __shfl_xor_sync(0xffffffffu, dot, off);

        float l = dot * 0.08838834764831845f + rel_bias[rel] + dir_bias[dj];
        float mn    = fmaxf(m, l);
        float alpha = __expf(m - mn);        // first active: exp(-3e38-l)=0
        float p     = __expf(l - mn);
        S = S * alpha + p;
        m = mn;
        #pragma unroll
        for (int i = 0; i < 8; i++) {
            aRe[i].x = aRe[i].x * alpha + p * hr[i].x;
            aRe[i].y = aRe[i].y * alpha + p * hr[i].y;
            aIm[i].x = aIm[i].x * alpha + p * hi[i].x;
            aIm[i].y = aIm[i].y * alpha + p * hi[i].y;
        }
    }

    if (lane == 0) { s_m[warp] = m; s_Sw[warp] = S; }
    __syncthreads();

    float gm = -3.0e38f;
    #pragma unroll
    for (int w = 0; w < 8; w++) gm = fmaxf(gm, s_m[w]);
    float Stot = 0.f;
    #pragma unroll
    for (int w = 0; w < 8; w++) Stot += s_Sw[w] * __expf(s_m[w] - gm);
    // this warp's contribution scale (all lanes of a warp hold identical m)
    float scale = (Stot > 0.f) ? (__expf(m - gm) / Stot) : 0.f;

    float2* accrow = (float2*)s_acc[warp];
    #pragma unroll
    for (int i = 0; i < 8; i++) {
        int f = lane + 32 * i;
        if (f < F2) {
            accrow[f]      = make_float2(aRe[i].x * scale, aRe[i].y * scale);
            accrow[F2 + f] = make_float2(aIm[i].x * scale, aIm[i].y * scale);
        }
    }
    __syncthreads();

    bool has = Stot > 0.f;
    float eta = 0.f;
    if (has) {
        float wsp = log1pf(__expf(w_raw[0]));          // softplus(w_raw)
        float lf  = log1pf(freq[aid]);
        float z   = eta_raw[0] - wsp * lf + b_p[0];
        eta = 0.5f / (1.f + __expf(-z));               // ETA_MAX * sigmoid
    }

    for (int d = tid; d < TWO_D; d += 256) {
        float delta = s_acc[0][d] + s_acc[1][d] + s_acc[2][d] + s_acc[3][d]
                    + s_acc[4][d] + s_acc[5][d] + s_acc[6][d] + s_acc[7][d];
        float ei = E[(size_t)aid * TWO_D + d];
        float ap = a_param[(d < DD) ? d : (d - DD)];
        float o  = has ? (ei + eta * (ap * delta - ei)) : ei;
        out[(size_t)bid * TWO_D + d] = o;
    }
}

extern "C" void kernel_launch(void* const* d_in, const int* in_sizes, int n_in,
                              void* d_out, int out_size) {
    const int*   anchor_ids = (const int*)  d_in[0];
    const int*   nbr_ent    = (const int*)  d_in[1];
    const int*   nbr_rel    = (const int*)  d_in[2];
    const void*  nbr_dir    =               d_in[3];
    const void*  nbr_mask   =               d_in[4];
    const float* freq       = (const float*)d_in[5];
    const float* E          = (const float*)d_in[6];
    const float* rel_phase  = (const float*)d_in[7];
    const float* a_param    = (const float*)d_in[8];
    const float* eta_raw    = (const float*)d_in[9];
    const float* w_raw      = (const float*)d_in[10];
    const float* b_p        = (const float*)d_in[11];
    const float* Wq         = (const float*)d_in[12];
    const float* Wk         = (const float*)d_in[13];
    const float* rel_bias   = (const float*)d_in[14];
    const float* dir_bias   = (const float*)d_in[15];
    float* out = (float*)d_out;

    prep_kernel<<<PREP_GRID, 256>>>(anchor_ids, E, Wq, Wk, rel_phase,
                                    (const unsigned int*)d_in[3]);
    refine_kernel<<<BB, 256>>>(anchor_ids, nbr_ent, nbr_rel, nbr_dir, nbr_mask,
                               freq, E, a_param, eta_raw, w_raw, b_p,
                               rel_bias, dir_bias, out);
}

// round 4
// speedup vs baseline: 1.8139x; 1.7322x over previous
#include <cuda_runtime.h>
#include <math.h>

#define N_ENT 100000
#define KN 64
#define DD 500
#define TWO_D 1000
#define RR 237
#define AT 128
#define BB 1024

// ---- device scratch (no allocations allowed) ----
__device__ int   g_bool_mode;          // 0=int32, 1=byte, 2=float32
__device__ float g_cos[RR * DD];
__device__ float g_sin[RR * DD];
__device__ float g_q[BB * AT];         // q_i = Wq e_i        [B, A]
__device__ float g_u[BB * TWO_D];      // u_i = Wk^T q_i      [B, 2D]

__device__ __forceinline__ int get_flag(const void* p, size_t i, int mode) {
    if (mode == 1) return ((const unsigned char*)p)[i] != 0;
    if (mode == 2) return ((const float*)p)[i] != 0.0f;
    return ((const int*)p)[i] != 0;
}

// block 0: bool-mode detect; blocks 1..: cos/sin tables
__global__ __launch_bounds__(256) void small_prep_kernel(
    const float* __restrict__ phase,
    const unsigned int* __restrict__ boolprobe)
{
    int blk = blockIdx.x, tid = threadIdx.x;
    if (blk == 0) {
        // int32 words always <=1; byte-packed bool words exceed 1 w.h.p. but
        // never 0x01010101; float 1.0f = 0x3F800000
        __shared__ int big1, big2;
        if (tid == 0) { big1 = 0; big2 = 0; }
        __syncthreads();
        for (int i = tid; i < 2048; i += 256) {
            unsigned v = boolprobe[i];
            if (v > 1u)          big1 = 1;
            if (v > 0x01010101u) big2 = 1;
        }
        __syncthreads();
        if (tid == 0) g_bool_mode = big2 ? 2 : (big1 ? 1 : 0);
    } else {
        int i = (blk - 1) * 256 + tid;
        if (i < RR * DD) {
            float s, c;
            sincosf(phase[i], &s, &c);
            g_cos[i] = c;
            g_sin[i] = s;
        }
    }
}

// q[b][a] = Wq[a] . e_b.  Grid (128, 4): 8 anchors x 32 attn rows per block.
__global__ __launch_bounds__(256) void q_kernel(
    const int*   __restrict__ anchor_ids,
    const float* __restrict__ E,
    const float* __restrict__ Wq)
{
    __shared__ float e_sm[8][TWO_D];
    __shared__ int aid_sm[8];
    int tid = threadIdx.x;
    int base = blockIdx.x * 8;
    if (tid < 8) aid_sm[tid] = anchor_ids[base + tid];
    __syncthreads();
    for (int idx = tid; idx < 8 * TWO_D; idx += 256) {
        int i = idx / TWO_D;
        int d = idx - i * TWO_D;
        e_sm[i][d] = E[(size_t)aid_sm[i] * TWO_D + d];
    }
    __syncthreads();

    int warp = tid >> 5, lane = tid & 31;
    int a0 = blockIdx.y * 32 + warp * 4;       // 4 attn rows per warp
    float acc[4][8];
    #pragma unroll
    for (int r = 0; r < 4; r++)
        #pragma unroll
        for (int i = 0; i < 8; i++) acc[r][i] = 0.f;
    for (int d = lane; d < TWO_D; d += 32) {
        float ev[8];
        #pragma unroll
        for (int i = 0; i < 8; i++) ev[i] = e_sm[i][d];
        #pragma unroll
        for (int r = 0; r < 4; r++) {
            float wv = Wq[(a0 + r) * TWO_D + d];
            #pragma unroll
            for (int i = 0; i < 8; i++) acc[r][i] += wv * ev[i];
        }
    }
    #pragma unroll
    for (int r = 0; r < 4; r++)
        #pragma unroll
        for (int i = 0; i < 8; i++) {
            float v = acc[r][i];
            #pragma unroll
            for (int off = 16; off; off >>= 1)
                v += __shfl_xor_sync(0xffffffffu, v, off);
            if (lane == 0) g_q[(size_t)(base + i) * AT + a0 + r] = v;
        }
}

// u[b][c] = sum_a q[b][a] Wk[a][c].  Grid (128, 4): 8 anchors x 256 cols.
__global__ __launch_bounds__(256) void u_kernel(
    const float* __restrict__ Wk)
{
    __shared__ float q_sm[8][AT];
    int tid = threadIdx.x;
    int base = blockIdx.x * 8;
    int c0 = blockIdx.y * 256;
    for (int idx = tid; idx < 8 * AT; idx += 256) {
        int i = idx >> 7, a = idx & 127;
        q_sm[i][a] = g_q[(size_t)(base + i) * AT + a];
    }
    __syncthreads();

    int c = c0 + tid;
    if (c < TWO_D) {
        float acc[8] = {0.f,0.f,0.f,0.f,0.f,0.f,0.f,0.f};
        for (int a = 0; a < AT; a += 4) {
            float w0 = Wk[(a+0) * TWO_D + c];
            float w1 = Wk[(a+1) * TWO_D + c];
            float w2 = Wk[(a+2) * TWO_D + c];
            float w3 = Wk[(a+3) * TWO_D + c];
            #pragma unroll
            for (int i = 0; i < 8; i++) {
                float4 q4 = *(const float4*)&q_sm[i][a];
                acc[i] += w0*q4.x + w1*q4.y + w2*q4.z + w3*q4.w;
            }
        }
        #pragma unroll
        for (int i = 0; i < 8; i++)
            g_u[(size_t)(base + i) * TWO_D + c] = acc[i];
    }
}

// Two-phase refine: Phase A streams gathered rows to produce logits only
// (no retention -> low regs, full MLP). Block softmax. Phase B re-gathers the
// same rows (L2-resident now) with known weights -> independent streaming FMA.
__global__ __launch_bounds__(256) void refine_kernel(
    const int*   __restrict__ anchor_ids,
    const int*   __restrict__ nbr_ent,
    const int*   __restrict__ nbr_rel,
    const void*  __restrict__ nbr_dir,
    const void*  __restrict__ nbr_mask,
    const float* __restrict__ freq,
    const float* __restrict__ E,
    const float* __restrict__ a_param,
    const float* __restrict__ eta_raw,
    const float* __restrict__ w_raw,
    const float* __restrict__ b_p,
    const float* __restrict__ rel_bias,
    const float* __restrict__ dir_bias,
    float*       __restrict__ out)
{
    __shared__ int s_ent[KN];
    __shared__ int s_rel[KN];
    __shared__ unsigned char s_dir[KN];
    __shared__ unsigned char s_msk[KN];
    __shared__ int s_act[KN];
    __shared__ int s_nact;
    __shared__ float s_w[KN];
    __shared__ __align__(16) float u_sm[TWO_D];

    int tid  = threadIdx.x;
    int bid  = blockIdx.x;
    int warp = tid >> 5, lane = tid & 31;
    int aid  = anchor_ids[bid];
    int mode = g_bool_mode;

    if (tid < KN) {
        size_t o = (size_t)aid * KN + tid;
        s_ent[tid] = nbr_ent[o];
        s_rel[tid] = nbr_rel[o];
        s_dir[tid] = (unsigned char)get_flag(nbr_dir, o, mode);
        s_msk[tid] = (unsigned char)get_flag(nbr_mask, o, mode);
    }
    for (int i = tid; i < TWO_D; i += 256)
        u_sm[i] = g_u[(size_t)bid * TWO_D + i];
    __syncthreads();

    // compact active neighbor list (warp 0)
    if (warp == 0) {
        unsigned b0 = __ballot_sync(0xffffffffu, s_msk[lane] != 0);
        unsigned b1 = __ballot_sync(0xffffffffu, s_msk[lane + 32] != 0);
        int n0 = __popc(b0);
        if (s_msk[lane])
            s_act[__popc(b0 & ((1u << lane) - 1u))] = lane;
        if (s_msk[lane + 32])
            s_act[n0 + __popc(b1 & ((1u << lane) - 1u))] = lane + 32;
        if (lane == 0) s_nact = n0 + __popc(b1);
    }
    __syncthreads();
    int nact = s_nact;

    if (nact > 0) {
        // ---- Phase A: logits ----
        const float4* u4 = (const float4*)u_sm;  // re: [g], im: [125+g]
        for (int ii = warp; ii < nact; ii += 8) {
            int j   = s_act[ii];
            int ent = s_ent[j];
            int rel = s_rel[j];
            int dj  = s_dir[j];
            const float4* er = (const float4*)(E + (size_t)ent * TWO_D);
            const float4* cr = (const float4*)(g_cos + rel * DD);
            const float4* sr = (const float4*)(g_sin + rel * DD);
            float sg = dj ? -1.f : 1.f;
            float dot = 0.f;
            #pragma unroll
            for (int k = 0; k < 4; k++) {
                int g = lane + 32 * k;
                if (g < 125) {
                    float4 re = er[g];
                    float4 im = er[125 + g];
                    float4 c  = cr[g];
                    float4 s  = sr[g];
                    float s0 = s.x*sg, s1 = s.y*sg, s2 = s.z*sg, s3 = s.w*sg;
                    float hr0 = re.x*c.x - im.x*s0;
                    float hr1 = re.y*c.y - im.y*s1;
                    float hr2 = re.z*c.z - im.z*s2;
                    float hr3 = re.w*c.w - im.w*s3;
                    float hi0 = re.x*s0 + im.x*c.x;
                    float hi1 = re.y*s1 + im.y*c.y;
                    float hi2 = re.z*s2 + im.z*c.z;
                    float hi3 = re.w*s3 + im.w*c.w;
                    float4 ur = u4[g], ui = u4[125 + g];
                    dot += ur.x*hr0 + ur.y*hr1 + ur.z*hr2 + ur.w*hr3
                         + ui.x*hi0 + ui.y*hi1 + ui.z*hi2 + ui.w*hi3;
                }
            }
            #pragma unroll
            for (int off = 16; off; off >>= 1)
                dot += __shfl_xor_sync(0xffffffffu, dot, off);
            if (lane == 0)
                s_w[ii] = dot * 0.08838834764831845f
                        + rel_bias[rel] + dir_bias[dj];
        }
        __syncthreads();

        // ---- softmax over s_w[0..nact) (warp 0) ----
        if (warp == 0) {
            float l0 = (lane      < nact) ? s_w[lane]      : -3.0e38f;
            float l1 = (lane + 32 < nact) ? s_w[lane + 32] : -3.0e38f;
            float mx = fmaxf(l0, l1);
            #pragma unroll
            for (int off = 16; off; off >>= 1)
                mx = fmaxf(mx, __shfl_xor_sync(0xffffffffu, mx, off));
            float e0 = (lane      < nact) ? __expf(l0 - mx) : 0.f;
            float e1 = (lane + 32 < nact) ? __expf(l1 - mx) : 0.f;
            float sm = e0 + e1;
            #pragma unroll
            for (int off = 16; off; off >>= 1)
                sm += __shfl_xor_sync(0xffffffffu, sm, off);
            float inv = 1.f / sm;
            if (lane      < nact) s_w[lane]      = e0 * inv;
            if (lane + 32 < nact) s_w[lane + 32] = e1 * inv;
        }
        __syncthreads();
    }

    // ---- Phase B: weighted accumulate (L2 hits) + epilogue ----
    // thread t < 250 owns re floats [2t,2t+1] and im floats [500+2t,501+2t]
    if (tid < 250) {
        int t = tid;
        float2 accRe = make_float2(0.f, 0.f);
        float2 accIm = make_float2(0.f, 0.f);
        for (int ii = 0; ii < nact; ii++) {
            int j   = s_act[ii];
            int ent = s_ent[j];
            int rel = s_rel[j];
            float w  = s_w[ii];
            float sg = s_dir[j] ? -1.f : 1.f;
            const float2* er = (const float2*)(E + (size_t)ent * TWO_D);
            float2 re = er[t];
            float2 im = er[250 + t];
            float2 c  = ((const float2*)(g_cos + rel * DD))[t];
            float2 s  = ((const float2*)(g_sin + rel * DD))[t];
            float s0 = s.x * sg, s1 = s.y * sg;
            accRe.x += w * (re.x*c.x - im.x*s0);
            accRe.y += w * (re.y*c.y - im.y*s1);
            accIm.x += w * (re.x*s0 + im.x*c.x);
            accIm.y += w * (re.y*s1 + im.y*c.y);
        }

        const float2* ei = (const float2*)(E + (size_t)aid * TWO_D);
        float2 eRe = ei[t];
        float2 eIm = ei[250 + t];
        float2 oRe = eRe, oIm = eIm;
        if (nact > 0) {
            float wsp = log1pf(__expf(w_raw[0]));          // softplus
            float lf  = log1pf(freq[aid]);
            float z   = eta_raw[0] - wsp * lf + b_p[0];
            float eta = 0.5f / (1.f + __expf(-z));         // ETA_MAX*sigmoid
            float2 ap = ((const float2*)a_param)[t];
            oRe.x = eRe.x + eta * (ap.x * accRe.x - eRe.x);
            oRe.y = eRe.y + eta * (ap.y * accRe.y - eRe.y);
            oIm.x = eIm.x + eta * (ap.x * accIm.x - eIm.x);
            oIm.y = eIm.y + eta * (ap.y * accIm.y - eIm.y);
        }
        ((float2*)(out + (size_t)bid * TWO_D))[t]       = oRe;
        ((float2*)(out + (size_t)bid * TWO_D))[250 + t] = oIm;
    }
}

extern "C" void kernel_launch(void* const* d_in, const int* in_sizes, int n_in,
                              void* d_out, int out_size) {
    const int*   anchor_ids = (const int*)  d_in[0];
    const int*   nbr_ent    = (const int*)  d_in[1];
    const int*   nbr_rel    = (const int*)  d_in[2];
    const void*  nbr_dir    =               d_in[3];
    const void*  nbr_mask   =               d_in[4];
    const float* freq       = (const float*)d_in[5];
    const float* E          = (const float*)d_in[6];
    const float* rel_phase  = (const float*)d_in[7];
    const float* a_param    = (const float*)d_in[8];
    const float* eta_raw    = (const float*)d_in[9];
    const float* w_raw      = (const float*)d_in[10];
    const float* b_p        = (const float*)d_in[11];
    const float* Wq         = (const float*)d_in[12];
    const float* Wk         = (const float*)d_in[13];
    const float* rel_bias   = (const float*)d_in[14];
    const float* dir_bias   = (const float*)d_in[15];
    float* out = (float*)d_out;

    small_prep_kernel<<<1 + (RR * DD + 255) / 256, 256>>>(
        rel_phase, (const unsigned int*)d_in[3]);
    q_kernel<<<dim3(BB / 8, 4), 256>>>(anchor_ids, E, Wq);
    u_kernel<<<dim3(BB / 8, 4), 256>>>(Wk);
    refine_kernel<<<BB, 256>>>(anchor_ids, nbr_ent, nbr_rel, nbr_dir, nbr_mask,
                               freq, E, a_param, eta_raw, w_raw, b_p,
                               rel_bias, dir_bias, out);
}